// round 5
// baseline (speedup 1.0000x reference)
#include <cuda_runtime.h>
#include <cuda_bf16.h>

// GCN layer:
//   deg[dst] += 1 over edges; dis = deg>0 ? rsqrt(deg) : 0
//   agg[dst] += nh[src] * dis[src]; x = agg * dis[:,None]
//   h = relu(x@W1+b1); out = h@W2+b2
//   output = concat(flatten(out), flatten(eh))
//
// Inputs resolved BY ELEMENT COUNT at runtime. Device-global scratch is
// referenced ONLY inside device code (host-side symbol = shadow var, and on
// GB300 ATS makes dereferencing it silently read zeros instead of trapping).

#define NN 100000
#define EE 1600000
#define DD 128

__device__ float g_deg[NN];
__device__ float g_dis[NN];
__device__ float g_agg[(size_t)NN * DD];
__device__ float g_hid[(size_t)NN * DD];
__device__ unsigned g_odd_or;   // 0 => edge_index is int64 (zero high halves)

// ---------- helpers ----------
__device__ __forceinline__ unsigned long long pack2(float a, float b) {
    unsigned long long r;
    asm("mov.b64 %0, {%1, %2};" : "=l"(r) : "f"(a), "f"(b));
    return r;
}
__device__ __forceinline__ void unpack2(unsigned long long v, float& a, float& b) {
    asm("mov.b64 {%0, %1}, %2;" : "=f"(a), "=f"(b) : "l"(v));
}
__device__ __forceinline__ void fma2(unsigned long long& d, unsigned long long a,
                                     unsigned long long b) {
    asm("fma.rn.f32x2 %0, %1, %2, %0;" : "+l"(d) : "l"(a), "l"(b));
}
__device__ __forceinline__ int edge_idx(const void* ei, int table, int e, bool is64) {
    if (is64) return (int)((const long long*)ei)[(size_t)table * EE + e];
    return ((const int*)ei)[(size_t)table * EE + e];
}

// ---------- kernel 0: zero scratch ----------
__global__ void zero_kernel() {
    int idx = blockIdx.x * blockDim.x + threadIdx.x;
    const int total4 = NN * DD / 4;
    if (idx < total4)
        reinterpret_cast<float4*>(g_agg)[idx] = make_float4(0.f, 0.f, 0.f, 0.f);
    if (idx < NN) g_deg[idx] = 0.f;
    if (idx == 0) g_odd_or = 0u;
}

// ---------- kernel 0b: detect int32 vs int64 edge_index ----------
// int64 (values < 2^31): every odd 32-bit word is 0. int32: odd words carry
// real indices (P(first 4096 all zero) ~ 0 for random data).
__global__ void detect_kernel(const unsigned* __restrict__ ei_words) {
    int t = blockIdx.x * blockDim.x + threadIdx.x;   // 4096 threads
    unsigned v = ei_words[2 * t + 1];
    #pragma unroll
    for (int o = 16; o > 0; o >>= 1) v |= __shfl_xor_sync(0xffffffffu, v, o);
    if ((threadIdx.x & 31) == 0 && v) atomicOr(&g_odd_or, v);
}

// ---------- kernel 1: degree ----------
__global__ void degree_kernel(const void* __restrict__ ei) {
    int e = blockIdx.x * blockDim.x + threadIdx.x;
    if (e >= EE) return;
    bool is64 = (g_odd_or == 0u);
    unsigned dst = (unsigned)edge_idx(ei, 1, e, is64);
    if (dst < NN) atomicAdd(&g_deg[dst], 1.0f);
}

// ---------- kernel 2: deg^{-1/2} ----------
__global__ void dis_kernel() {
    int i = blockIdx.x * blockDim.x + threadIdx.x;
    if (i < NN) {
        float d = g_deg[i];
        g_dis[i] = (d > 0.f) ? rsqrtf(d) : 0.f;
    }
}

// ---------- kernel 3: scatter (one warp per edge, scalar f32 RED) ----------
// Lane handles elements {lane+32j}: each LDG/RED warp-instruction covers a
// contiguous 128B span (4 sectors).
__global__ void scatter_kernel(const void* __restrict__ ei,
                               const float* __restrict__ nh) {
    int w = (blockIdx.x * blockDim.x + threadIdx.x) >> 5;
    int lane = threadIdx.x & 31;
    if (w >= EE) return;
    bool is64 = (g_odd_or == 0u);
    unsigned src = (unsigned)edge_idx(ei, 0, w, is64);
    unsigned dst = (unsigned)edge_idx(ei, 1, w, is64);
    if (src >= NN || dst >= NN) return;
    float s = __ldg(&g_dis[src]);
    const float* np = nh + (size_t)src * DD;
    float* ap = g_agg + (size_t)dst * DD;
    #pragma unroll
    for (int j = 0; j < 4; ++j) {
        int idx = lane + 32 * j;
        atomicAdd(ap + idx, __ldg(np + idx) * s);
    }
}

// ---------- kernel 4: 128x128 GEMM, 8 rows/block, f32x2 FMA ----------
// FIRST=true : X = g_agg * g_dis[row], Y = g_hid, relu.
// FIRST=false: X = g_hid, Y = Yext (harness d_out), no relu.
// Device-global scratch referenced directly — never passed from host.
// Thread j computes output column j for 8 rows as 4 packed f32x2
// accumulators (row pairs); x staged transposed in smem so row pairs load
// as one LDS64. W column read via L1 (64KB, resident within launch).
template<bool FIRST>
__global__ void __launch_bounds__(128) gemm_kernel(
    const float* __restrict__ W, const float* __restrict__ bias,
    float* __restrict__ Yext) {
    __shared__ __align__(16) float xs[DD][8];
    const int tid = threadIdx.x;            // output column j
    const int row0 = blockIdx.x * 8;

    const float* X = FIRST ? g_agg : g_hid;
    #pragma unroll
    for (int r = 0; r < 8; ++r) {
        float v = X[(size_t)(row0 + r) * DD + tid];
        if (FIRST) v *= __ldg(&g_dis[row0 + r]);
        xs[tid][r] = v;
    }
    __syncthreads();

    float bj = __ldg(&bias[tid]);
    unsigned long long acc0 = pack2(bj, bj);
    unsigned long long acc1 = acc0, acc2 = acc0, acc3 = acc0;

    #pragma unroll 8
    for (int k = 0; k < DD; ++k) {
        float w = __ldg(&W[k * DD + tid]);
        unsigned long long ww = pack2(w, w);
        const unsigned long long* xp =
            reinterpret_cast<const unsigned long long*>(&xs[k][0]);
        fma2(acc0, xp[0], ww);
        fma2(acc1, xp[1], ww);
        fma2(acc2, xp[2], ww);
        fma2(acc3, xp[3], ww);
    }

    float* Y = FIRST ? g_hid : Yext;
    unsigned long long accs[4] = {acc0, acc1, acc2, acc3};
    #pragma unroll
    for (int pr = 0; pr < 4; ++pr) {
        float lo, hi;
        unpack2(accs[pr], lo, hi);
        if (FIRST) { lo = fmaxf(lo, 0.f); hi = fmaxf(hi, 0.f); }
        Y[(size_t)(row0 + 2 * pr)     * DD + tid] = lo;
        Y[(size_t)(row0 + 2 * pr + 1) * DD + tid] = hi;
    }
}

// ---------- kernel 5: eh passthrough ----------
__global__ void copy_eh_kernel(const float* __restrict__ eh, float* __restrict__ out) {
    int idx = blockIdx.x * blockDim.x + threadIdx.x;
    const int total4 = EE * 16 / 4;
    if (idx < total4)
        reinterpret_cast<float4*>(out)[idx] =
            __ldg(reinterpret_cast<const float4*>(eh) + idx);
}

extern "C" void kernel_launch(void* const* d_in, const int* in_sizes, int n_in,
                              void* d_out, int out_size) {
    // Resolve inputs by element count (robust to metadata ordering as long
    // as W1 precedes W2 and b1 precedes b2 — true for dict AND sorted order).
    const float* nh = nullptr; const float* eh = nullptr; const void* ei = nullptr;
    const float* Wp[2] = {nullptr, nullptr}; const float* bp[2] = {nullptr, nullptr};
    int nw = 0, nb = 0;
    for (int i = 0; i < n_in; ++i) {
        int s = in_sizes[i];
        if (s == NN * DD)            nh = (const float*)d_in[i];      // 12,800,000
        else if (s == EE * 16)       eh = (const float*)d_in[i];      // 25,600,000
        else if (s == 2 * EE)        ei = d_in[i];                    //  3,200,000
        else if (s == DD * DD) { if (nw < 2) Wp[nw++] = (const float*)d_in[i]; }
        else if (s == DD)      { if (nb < 2) bp[nb++] = (const float*)d_in[i]; }
    }
    const float* W1 = Wp[0]; const float* b1 = bp[0];
    const float* W2 = Wp[1]; const float* b2 = bp[1];
    float* out = (float*)d_out;

    zero_kernel<<<(NN * DD / 4 + 255) / 256, 256>>>();
    detect_kernel<<<16, 256>>>((const unsigned*)ei);
    degree_kernel<<<(EE + 255) / 256, 256>>>(ei);
    dis_kernel<<<(NN + 255) / 256, 256>>>();
    scatter_kernel<<<EE / 8, 256>>>(ei, nh);
    gemm_kernel<true ><<<NN / 8, 128>>>(W1, b1, nullptr);
    gemm_kernel<false><<<NN / 8, 128>>>(W2, b2, out);
    copy_eh_kernel<<<(EE * 16 / 4 + 255) / 256, 256>>>(eh, out + (size_t)NN * DD);
}

// round 6
// speedup vs baseline: 1.5855x; 1.5855x over previous
#include <cuda_runtime.h>
#include <cuda_bf16.h>
#include <cstdint>

// GCN layer on GB300. Pipeline:
//   zero -> detect idx dtype -> degree -> dis=rsqrt(deg) ->
//   scatter (v4 f32 RED, warp=edge) -> GEMM1 (tf32 mma, relu, *dis) ->
//   GEMM2 (tf32 mma) -> eh passthrough copy.
// Scratch lives in __device__ globals referenced ONLY from device code.

#define NN 100000
#define EE 1600000
#define DD 128
#define MTILES 6250   // 100000/16

__device__ __align__(128) float g_deg[NN];
__device__ __align__(128) float g_dis[NN];
__device__ __align__(128) float g_agg[(size_t)NN * DD];
__device__ __align__(128) float g_hid[(size_t)NN * DD];
__device__ unsigned g_odd_or;   // 0 => edge_index is int64 (zero high words)

// ---------- helpers ----------
__device__ __forceinline__ int edge_idx(const void* ei, int table, long long e, bool is64) {
    if (is64) return (int)((const long long*)ei)[(size_t)table * EE + e];
    return ((const int*)ei)[(size_t)table * EE + e];
}
__device__ __forceinline__ uint32_t cvt_tf32(float x) {
    uint32_t r;
    asm("cvt.rna.tf32.f32 %0, %1;" : "=r"(r) : "f"(x));
    return r;
}
__device__ __forceinline__ void mma_tf32(float c[4], uint32_t a0, uint32_t a1,
                                         uint32_t a2, uint32_t a3,
                                         uint32_t b0, uint32_t b1) {
    asm volatile(
        "mma.sync.aligned.m16n8k8.row.col.f32.tf32.tf32.f32 "
        "{%0,%1,%2,%3}, {%4,%5,%6,%7}, {%8,%9}, {%0,%1,%2,%3};"
        : "+f"(c[0]), "+f"(c[1]), "+f"(c[2]), "+f"(c[3])
        : "r"(a0), "r"(a1), "r"(a2), "r"(a3), "r"(b0), "r"(b1));
}

// ---------- kernel 0: zero scratch ----------
__global__ void zero_kernel() {
    int idx = blockIdx.x * blockDim.x + threadIdx.x;
    const int total4 = NN * DD / 4;
    if (idx < total4)
        reinterpret_cast<float4*>(g_agg)[idx] = make_float4(0.f, 0.f, 0.f, 0.f);
    if (idx < NN) g_deg[idx] = 0.f;
    if (idx == 0) g_odd_or = 0u;
}

// ---------- kernel 0b: detect int32 vs int64 edge_index ----------
__global__ void detect_kernel(const unsigned* __restrict__ ei_words) {
    int t = blockIdx.x * blockDim.x + threadIdx.x;   // 4096 threads
    unsigned v = ei_words[2 * t + 1];
    #pragma unroll
    for (int o = 16; o > 0; o >>= 1) v |= __shfl_xor_sync(0xffffffffu, v, o);
    if ((threadIdx.x & 31) == 0 && v) atomicOr(&g_odd_or, v);
}

// ---------- kernel 1: degree ----------
__global__ void degree_kernel(const void* __restrict__ ei) {
    int e = blockIdx.x * blockDim.x + threadIdx.x;
    if (e >= EE) return;
    bool is64 = (g_odd_or == 0u);
    unsigned dst = (unsigned)edge_idx(ei, 1, e, is64);
    if (dst < NN) atomicAdd(&g_deg[dst], 1.0f);
}

// ---------- kernel 2: deg^{-1/2} ----------
__global__ void dis_kernel() {
    int i = blockIdx.x * blockDim.x + threadIdx.x;
    if (i < NN) {
        float d = g_deg[i];
        g_dis[i] = (d > 0.f) ? rsqrtf(d) : 0.f;
    }
}

// ---------- kernel 3: scatter ----------
// Warp processes 32 edges: coalesced per-lane loads of src/dst/dis, then
// broadcast via shuffle. Per edge: one LDG.128 (512B row gather) + one
// red.global.add.v4.f32 (512B contiguous RMW). EE = 32*50000 exactly.
__global__ void scatter_kernel(const void* __restrict__ ei,
                               const float* __restrict__ nh) {
    int w = (blockIdx.x * blockDim.x + threadIdx.x) >> 5;
    int lane = threadIdx.x & 31;
    long long base = (long long)w * 32;
    if (base >= EE) return;
    bool is64 = (g_odd_or == 0u);
    long long e = base + lane;
    int my_src = edge_idx(ei, 0, e, is64);
    int my_dst = edge_idx(ei, 1, e, is64);
    float my_s = ((unsigned)my_src < NN) ? __ldg(&g_dis[my_src]) : 0.f;

    #pragma unroll 4
    for (int i = 0; i < 32; ++i) {
        int src = __shfl_sync(0xffffffffu, my_src, i);
        int dst = __shfl_sync(0xffffffffu, my_dst, i);
        float s = __shfl_sync(0xffffffffu, my_s, i);
        if ((unsigned)src >= NN || (unsigned)dst >= NN) continue;
        float4 v = __ldg(reinterpret_cast<const float4*>(nh) + (size_t)src * 32 + lane);
        float* p = g_agg + (size_t)dst * DD + lane * 4;
        asm volatile("red.global.add.v4.f32 [%0], {%1, %2, %3, %4};"
                     :: "l"(p), "f"(v.x * s), "f"(v.y * s), "f"(v.z * s), "f"(v.w * s)
                     : "memory");
    }
}

// ---------- kernel 4: GEMM via tf32 mma.sync (m16n8k8) ----------
// FIRST=true : X = g_agg * dis[row], Y = g_hid, relu.
// FIRST=false: X = g_hid,            Y = Yext.
// Block = 4 warps; warp handles one m16 x n128 stripe (16 n8 tiles).
// W chunked into smem 32(k) x 132(pad) as RNA-rounded tf32 bit patterns.
template<bool FIRST>
__global__ void __launch_bounds__(128) gemm_tc(
    const float* __restrict__ W, const float* __restrict__ bias,
    float* __restrict__ Yext) {
    __shared__ float sB[32][132];
    const int tid = threadIdx.x, lane = tid & 31, warp = tid >> 5;
    const int gid = lane >> 2, tq = lane & 3;
    const int mtile = blockIdx.x * 4 + warp;
    const bool active = mtile < MTILES;
    const size_t r0 = (size_t)mtile * 16 + gid, r1 = r0 + 8;
    const float* X = FIRST ? g_agg : g_hid;

    float dis0 = 1.f, dis1 = 1.f;
    if (FIRST && active) { dis0 = __ldg(&g_dis[r0]); dis1 = __ldg(&g_dis[r1]); }

    float acc[16][4];
    #pragma unroll
    for (int t = 0; t < 16; ++t)
        acc[t][0] = acc[t][1] = acc[t][2] = acc[t][3] = 0.f;

    for (int c = 0; c < 4; ++c) {            // k-chunks of 32
        __syncthreads();                      // protect prior chunk's readers
        #pragma unroll
        for (int i = 0; i < 8; ++i) {         // 1024 float4 by 128 threads
            int idx = tid + i * 128;
            int row = idx >> 5, n4 = idx & 31;
            float4 w4 = __ldg(reinterpret_cast<const float4*>(
                                  W + (size_t)(c * 32 + row) * DD) + n4);
            // Store RNA-rounded tf32 bit patterns (unbiased — truncation
            // would bias 128-sums by ~5e-4 per GEMM).
            sB[row][n4 * 4 + 0] = __uint_as_float(cvt_tf32(w4.x));
            sB[row][n4 * 4 + 1] = __uint_as_float(cvt_tf32(w4.y));
            sB[row][n4 * 4 + 2] = __uint_as_float(cvt_tf32(w4.z));
            sB[row][n4 * 4 + 3] = __uint_as_float(cvt_tf32(w4.w));
        }
        __syncthreads();

        if (active) {
            #pragma unroll
            for (int ki = 0; ki < 4; ++ki) {  // k8 steps within chunk
                int k = c * 32 + ki * 8 + tq;
                float x0 = X[r0 * DD + k],     x1 = X[r1 * DD + k];
                float x2 = X[r0 * DD + k + 4], x3 = X[r1 * DD + k + 4];
                if (FIRST) { x0 *= dis0; x1 *= dis1; x2 *= dis0; x3 *= dis1; }
                uint32_t a0 = cvt_tf32(x0), a1 = cvt_tf32(x1);
                uint32_t a2 = cvt_tf32(x2), a3 = cvt_tf32(x3);
                int kl = ki * 8 + tq;
                #pragma unroll
                for (int t = 0; t < 16; ++t) {
                    uint32_t b0 = __float_as_uint(sB[kl][8 * t + gid]);
                    uint32_t b1 = __float_as_uint(sB[kl + 4][8 * t + gid]);
                    mma_tf32(acc[t], a0, a1, a2, a3, b0, b1);
                }
            }
        }
    }

    if (active) {
        float* Y = FIRST ? g_hid : Yext;
        #pragma unroll
        for (int t = 0; t < 16; ++t) {
            int n = 8 * t + 2 * tq;
            float2 bb = __ldg(reinterpret_cast<const float2*>(bias + n));
            float v0 = acc[t][0] + bb.x, v1 = acc[t][1] + bb.y;
            float v2 = acc[t][2] + bb.x, v3 = acc[t][3] + bb.y;
            if (FIRST) {
                v0 = fmaxf(v0, 0.f); v1 = fmaxf(v1, 0.f);
                v2 = fmaxf(v2, 0.f); v3 = fmaxf(v3, 0.f);
            }
            *reinterpret_cast<float2*>(Y + r0 * DD + n) = make_float2(v0, v1);
            *reinterpret_cast<float2*>(Y + r1 * DD + n) = make_float2(v2, v3);
        }
    }
}

// ---------- kernel 5: eh passthrough ----------
__global__ void copy_eh_kernel(const float* __restrict__ eh, float* __restrict__ out) {
    int idx = blockIdx.x * blockDim.x + threadIdx.x;
    const int total4 = EE * 16 / 4;
    if (idx < total4)
        reinterpret_cast<float4*>(out)[idx] =
            __ldg(reinterpret_cast<const float4*>(eh) + idx);
}

extern "C" void kernel_launch(void* const* d_in, const int* in_sizes, int n_in,
                              void* d_out, int out_size) {
    // Resolve inputs by element count (order-agnostic as long as W1 precedes
    // W2 and b1 precedes b2 — true for dict and alphabetical orders).
    const float* nh = nullptr; const float* eh = nullptr; const void* ei = nullptr;
    const float* Wp[2] = {nullptr, nullptr}; const float* bp[2] = {nullptr, nullptr};
    int nw = 0, nb = 0;
    for (int i = 0; i < n_in; ++i) {
        int s = in_sizes[i];
        if (s == NN * DD)            nh = (const float*)d_in[i];
        else if (s == EE * 16)       eh = (const float*)d_in[i];
        else if (s == 2 * EE)        ei = d_in[i];
        else if (s == DD * DD) { if (nw < 2) Wp[nw++] = (const float*)d_in[i]; }
        else if (s == DD)      { if (nb < 2) bp[nb++] = (const float*)d_in[i]; }
    }
    float* out = (float*)d_out;

    zero_kernel<<<(NN * DD / 4 + 255) / 256, 256>>>();
    detect_kernel<<<16, 256>>>((const unsigned*)ei);
    degree_kernel<<<(EE + 255) / 256, 256>>>(ei);
    dis_kernel<<<(NN + 255) / 256, 256>>>();
    scatter_kernel<<<EE / 32 / 8, 256>>>(ei, nh);                 // 6250 blocks
    gemm_tc<true ><<<(MTILES + 3) / 4, 128>>>(Wp[0], bp[0], nullptr);
    gemm_tc<false><<<(MTILES + 3) / 4, 128>>>(Wp[1], bp[1], out);
    copy_eh_kernel<<<(EE * 16 / 4 + 255) / 256, 256>>>(eh, out + (size_t)NN * DD);
}

// round 7
// speedup vs baseline: 1.9582x; 1.2351x over previous
#include <cuda_runtime.h>
#include <cuda_bf16.h>
#include <cstdint>

// GCN layer on GB300, CSR-based aggregation (no feature-width atomics):
//   cnt[dst]++  ->  exclusive scan -> bucket-fill edge srcs ->
//   warp-per-dst gather/accumulate (agg = sum(nh[src]*dis[src]) * dis[dst])
//   -> GEMM1 tf32 (relu) -> GEMM2 tf32 -> eh passthrough.
// Scratch in __device__ globals referenced only from device code.

#define NN 100000
#define EE 1600000
#define DD 128
#define MTILES 6250        // 100000/16
#define NBLK 391           // ceil(NN/256)

__device__ __align__(128) int   g_cnt[NN];
__device__ __align__(128) int   g_off[NN];
__device__ __align__(128) int   g_cur[NN];
__device__ __align__(128) int   g_bsum[512];
__device__ __align__(128) int   g_bscan[512];
__device__ __align__(128) int   g_esrc[EE];
__device__ __align__(128) float g_dis[NN];
__device__ __align__(128) float g_agg[(size_t)NN * DD];
__device__ __align__(128) float g_hid[(size_t)NN * DD];
__device__ unsigned g_odd_or;   // 0 => edge_index is int64 (zero high words)

// ---------- helpers ----------
__device__ __forceinline__ int edge_idx(const void* ei, int table, int e, bool is64) {
    if (is64) return (int)((const long long*)ei)[(size_t)table * EE + e];
    return ((const int*)ei)[(size_t)table * EE + e];
}
__device__ __forceinline__ uint32_t cvt_tf32(float x) {
    uint32_t r;
    asm("cvt.rna.tf32.f32 %0, %1;" : "=r"(r) : "f"(x));
    return r;
}
__device__ __forceinline__ void mma_tf32(float c[4], uint32_t a0, uint32_t a1,
                                         uint32_t a2, uint32_t a3,
                                         uint32_t b0, uint32_t b1) {
    asm volatile(
        "mma.sync.aligned.m16n8k8.row.col.f32.tf32.tf32.f32 "
        "{%0,%1,%2,%3}, {%4,%5,%6,%7}, {%8,%9}, {%0,%1,%2,%3};"
        : "+f"(c[0]), "+f"(c[1]), "+f"(c[2]), "+f"(c[3])
        : "r"(a0), "r"(a1), "r"(a2), "r"(a3), "r"(b0), "r"(b1));
}

// ---------- zero counters ----------
__global__ void zero_kernel() {
    int i = blockIdx.x * blockDim.x + threadIdx.x;
    if (i < NN) g_cnt[i] = 0;
    if (i == 0) g_odd_or = 0u;
}

// ---------- detect int32 vs int64 edge_index ----------
__global__ void detect_kernel(const unsigned* __restrict__ ei_words) {
    int t = blockIdx.x * blockDim.x + threadIdx.x;   // 4096 threads
    unsigned v = ei_words[2 * t + 1];
    #pragma unroll
    for (int o = 16; o > 0; o >>= 1) v |= __shfl_xor_sync(0xffffffffu, v, o);
    if ((threadIdx.x & 31) == 0 && v) atomicOr(&g_odd_or, v);
}

// ---------- degree histogram (int) ----------
__global__ void degree_kernel(const void* __restrict__ ei) {
    int e = blockIdx.x * blockDim.x + threadIdx.x;
    if (e >= EE) return;
    bool is64 = (g_odd_or == 0u);
    unsigned dst = (unsigned)edge_idx(ei, 1, e, is64);
    if (dst < NN) atomicAdd(&g_cnt[dst], 1);
}

// ---------- scan pass 1: per-block sums ----------
__global__ void block_sum_kernel() {
    __shared__ int s[256];
    int i = blockIdx.x * 256 + threadIdx.x;
    s[threadIdx.x] = (i < NN) ? g_cnt[i] : 0;
    __syncthreads();
    #pragma unroll
    for (int o = 128; o > 0; o >>= 1) {
        if (threadIdx.x < o) s[threadIdx.x] += s[threadIdx.x + o];
        __syncthreads();
    }
    if (threadIdx.x == 0) g_bsum[blockIdx.x] = s[0];
}

// ---------- scan pass 2: exclusive scan of block sums (single block) ----------
__global__ void scan_bsum_kernel() {
    __shared__ int s[512];
    int t = threadIdx.x;
    int v = (t < NBLK) ? g_bsum[t] : 0;
    s[t] = v;
    __syncthreads();
    #pragma unroll
    for (int o = 1; o < 512; o <<= 1) {
        int x = (t >= o) ? s[t - o] : 0;
        __syncthreads();
        s[t] += x;
        __syncthreads();
    }
    if (t < NBLK) g_bscan[t] = s[t] - v;   // exclusive
}

// ---------- scan pass 3: per-element offsets + cursors + dis ----------
__global__ void finalize_kernel() {
    __shared__ int s[256];
    int i = blockIdx.x * 256 + threadIdx.x;
    int v = (i < NN) ? g_cnt[i] : 0;
    s[threadIdx.x] = v;
    __syncthreads();
    #pragma unroll
    for (int o = 1; o < 256; o <<= 1) {
        int x = (threadIdx.x >= o) ? s[threadIdx.x - o] : 0;
        __syncthreads();
        s[threadIdx.x] += x;
        __syncthreads();
    }
    if (i < NN) {
        int off = g_bscan[blockIdx.x] + s[threadIdx.x] - v;   // exclusive
        g_off[i] = off;
        g_cur[i] = off;
        g_dis[i] = (v > 0) ? rsqrtf((float)v) : 0.f;
    }
}

// ---------- bucket fill ----------
__global__ void fill_kernel(const void* __restrict__ ei) {
    int e = blockIdx.x * blockDim.x + threadIdx.x;
    if (e >= EE) return;
    bool is64 = (g_odd_or == 0u);
    int src = edge_idx(ei, 0, e, is64);
    int dst = edge_idx(ei, 1, e, is64);
    if ((unsigned)src >= NN || (unsigned)dst >= NN) return;
    int pos = atomicAdd(&g_cur[dst], 1);
    g_esrc[pos] = src;
}

// ---------- aggregate: warp per destination node ----------
// agg[d] = (sum_{e in CSR[d]} nh[src_e] * dis[src_e]) * dis[d]
__global__ void aggregate_kernel(const float* __restrict__ nh) {
    int w = (blockIdx.x * blockDim.x + threadIdx.x) >> 5;
    int lane = threadIdx.x & 31;
    if (w >= NN) return;
    int off = g_off[w], len = g_cnt[w];
    float4 acc = make_float4(0.f, 0.f, 0.f, 0.f);
    for (int b = 0; b < len; b += 32) {
        int n = min(32, len - b);
        int src = (lane < n) ? __ldg(&g_esrc[off + b + lane]) : 0;
        float s  = (lane < n) ? __ldg(&g_dis[src]) : 0.f;
        for (int i = 0; i < n; ++i) {
            int  ss = __shfl_sync(0xffffffffu, src, i);
            float sv = __shfl_sync(0xffffffffu, s, i);
            float4 v = __ldg(reinterpret_cast<const float4*>(nh) + (size_t)ss * 32 + lane);
            acc.x += v.x * sv; acc.y += v.y * sv;
            acc.z += v.z * sv; acc.w += v.w * sv;
        }
    }
    float dd = g_dis[w];
    acc.x *= dd; acc.y *= dd; acc.z *= dd; acc.w *= dd;
    reinterpret_cast<float4*>(g_agg)[(size_t)w * 32 + lane] = acc;
}

// ---------- GEMM via tf32 mma.sync (m16n8k8) ----------
// FIRST=true : X = g_agg (pre-scaled), Y = g_hid, relu.
// FIRST=false: X = g_hid, Y = Yext.
template<bool FIRST>
__global__ void __launch_bounds__(128) gemm_tc(
    const float* __restrict__ W, const float* __restrict__ bias,
    float* __restrict__ Yext) {
    __shared__ float sB[32][132];
    const int tid = threadIdx.x, lane = tid & 31, warp = tid >> 5;
    const int gid = lane >> 2, tq = lane & 3;
    const int mtile = blockIdx.x * 4 + warp;
    const bool active = mtile < MTILES;
    const size_t r0 = (size_t)mtile * 16 + gid, r1 = r0 + 8;
    const float* X = FIRST ? g_agg : g_hid;

    float acc[16][4];
    #pragma unroll
    for (int t = 0; t < 16; ++t)
        acc[t][0] = acc[t][1] = acc[t][2] = acc[t][3] = 0.f;

    for (int c = 0; c < 4; ++c) {            // k-chunks of 32
        __syncthreads();
        #pragma unroll
        for (int i = 0; i < 8; ++i) {
            int idx = tid + i * 128;
            int row = idx >> 5, n4 = idx & 31;
            float4 w4 = __ldg(reinterpret_cast<const float4*>(
                                  W + (size_t)(c * 32 + row) * DD) + n4);
            sB[row][n4 * 4 + 0] = __uint_as_float(cvt_tf32(w4.x));
            sB[row][n4 * 4 + 1] = __uint_as_float(cvt_tf32(w4.y));
            sB[row][n4 * 4 + 2] = __uint_as_float(cvt_tf32(w4.z));
            sB[row][n4 * 4 + 3] = __uint_as_float(cvt_tf32(w4.w));
        }
        __syncthreads();

        if (active) {
            #pragma unroll
            for (int ki = 0; ki < 4; ++ki) {
                int k = c * 32 + ki * 8 + tq;
                uint32_t a0 = cvt_tf32(X[r0 * DD + k]);
                uint32_t a1 = cvt_tf32(X[r1 * DD + k]);
                uint32_t a2 = cvt_tf32(X[r0 * DD + k + 4]);
                uint32_t a3 = cvt_tf32(X[r1 * DD + k + 4]);
                int kl = ki * 8 + tq;
                #pragma unroll
                for (int t = 0; t < 16; ++t) {
                    uint32_t b0 = __float_as_uint(sB[kl][8 * t + gid]);
                    uint32_t b1 = __float_as_uint(sB[kl + 4][8 * t + gid]);
                    mma_tf32(acc[t], a0, a1, a2, a3, b0, b1);
                }
            }
        }
    }

    if (active) {
        float* Y = FIRST ? g_hid : Yext;
        #pragma unroll
        for (int t = 0; t < 16; ++t) {
            int n = 8 * t + 2 * tq;
            float2 bb = __ldg(reinterpret_cast<const float2*>(bias + n));
            float v0 = acc[t][0] + bb.x, v1 = acc[t][1] + bb.y;
            float v2 = acc[t][2] + bb.x, v3 = acc[t][3] + bb.y;
            if (FIRST) {
                v0 = fmaxf(v0, 0.f); v1 = fmaxf(v1, 0.f);
                v2 = fmaxf(v2, 0.f); v3 = fmaxf(v3, 0.f);
            }
            *reinterpret_cast<float2*>(Y + r0 * DD + n) = make_float2(v0, v1);
            *reinterpret_cast<float2*>(Y + r1 * DD + n) = make_float2(v2, v3);
        }
    }
}

// ---------- eh passthrough ----------
__global__ void copy_eh_kernel(const float* __restrict__ eh, float* __restrict__ out) {
    int idx = blockIdx.x * blockDim.x + threadIdx.x;
    const int total4 = EE * 16 / 4;
    if (idx < total4)
        reinterpret_cast<float4*>(out)[idx] =
            __ldg(reinterpret_cast<const float4*>(eh) + idx);
}

extern "C" void kernel_launch(void* const* d_in, const int* in_sizes, int n_in,
                              void* d_out, int out_size) {
    const float* nh = nullptr; const float* eh = nullptr; const void* ei = nullptr;
    const float* Wp[2] = {nullptr, nullptr}; const float* bp[2] = {nullptr, nullptr};
    int nw = 0, nb = 0;
    for (int i = 0; i < n_in; ++i) {
        int s = in_sizes[i];
        if (s == NN * DD)            nh = (const float*)d_in[i];
        else if (s == EE * 16)       eh = (const float*)d_in[i];
        else if (s == 2 * EE)        ei = d_in[i];
        else if (s == DD * DD) { if (nw < 2) Wp[nw++] = (const float*)d_in[i]; }
        else if (s == DD)      { if (nb < 2) bp[nb++] = (const float*)d_in[i]; }
    }
    float* out = (float*)d_out;

    zero_kernel<<<NBLK, 256>>>();
    detect_kernel<<<16, 256>>>((const unsigned*)ei);
    degree_kernel<<<(EE + 255) / 256, 256>>>(ei);
    block_sum_kernel<<<NBLK, 256>>>();
    scan_bsum_kernel<<<1, 512>>>();
    finalize_kernel<<<NBLK, 256>>>();
    fill_kernel<<<(EE + 255) / 256, 256>>>(ei);
    aggregate_kernel<<<(NN * 32 + 255) / 256, 256>>>(nh);
    gemm_tc<true ><<<(MTILES + 3) / 4, 128>>>(Wp[0], bp[0], nullptr);
    gemm_tc<false><<<(MTILES + 3) / 4, 128>>>(Wp[1], bp[1], out);
    copy_eh_kernel<<<(EE * 16 / 4 + 255) / 256, 256>>>(eh, out + (size_t)NN * DD);
}